// round 9
// baseline (speedup 1.0000x reference)
#include <cuda_runtime.h>
#include <cuda_bf16.h>

#define NB 64      // batch
#define NL 512     // sequence length
#define ND 300     // embed dim
#define ND4 75     // float4 lanes per row
#define NC 128     // channels
#define CH 8       // token chunks per batch
#define TPC 64     // tokens per gather block
#define WAYS 4
#define JPER 16    // tokens per way

// Scratch (__device__ globals per allocation rules)
__device__ float4 g_part4[NB * CH * 3 * ND4];  // partial g sums

// ---------------------------------------------------------------------------
// Kernel 1: embedding gather + weighted partial reduction.  (unchanged — at
// its DRAM floor per R8 profile)
// ---------------------------------------------------------------------------
__global__ __launch_bounds__(320, 3) void gather_kernel(
    const int*   __restrict__ x,
    const float* __restrict__ embed_w,
    const float* __restrict__ fc3_w,
    const float* __restrict__ fc4_w,
    const float* __restrict__ fc5_w)
{
    const int b     = blockIdx.x >> 3;
    const int chunk = blockIdx.x & 7;

    __shared__ int    sidx[TPC];
    __shared__ float  sc[3][TPC];
    __shared__ float4 sred[WAYS][3][80];

    const int tid = threadIdx.x;
    const int d4  = tid % 80;
    const int y   = tid / 80;

    if (tid < 192) {
        const int kk = tid >> 6;
        const int tt = tid & 63;
        const int t  = chunk * TPC + tt;
        const float* wk = (kk == 0) ? fc3_w : (kk == 1) ? fc4_w : fc5_w;
        const int k = kk + 3;
        int lo = t - k + 1; if (lo < 0) lo = 0;
        int hi = t; const int lim = NL - k - 1; if (hi > lim) hi = lim;
        float s = 0.f;
        #pragma unroll 5
        for (int l = lo; l <= hi; l++) s += __ldg(&wk[l]);
        sc[kk][tt] = s;
    } else if (tid < 256) {
        const int tt = tid - 192;
        sidx[tt] = __ldg(&x[b * NL + chunk * TPC + tt]);
    }
    __syncthreads();

    float4 a0 = make_float4(0.f, 0.f, 0.f, 0.f);
    float4 a1 = a0, a2 = a0;

    if (d4 < ND4) {
        const float4* emb4 = (const float4*)embed_w;
        #pragma unroll
        for (int bb = 0; bb < 2; bb++) {
            int    rix[8];
            float4 v[8];
            #pragma unroll
            for (int j = 0; j < 8; j++) rix[j] = sidx[y * JPER + bb * 8 + j];
            #pragma unroll
            for (int j = 0; j < 8; j++) v[j] = __ldg(&emb4[rix[j] * ND4 + d4]);
            #pragma unroll
            for (int j = 0; j < 8; j++) {
                const int jj = y * JPER + bb * 8 + j;
                const float c0 = sc[0][jj], c1 = sc[1][jj], c2 = sc[2][jj];
                a0.x = fmaf(c0, v[j].x, a0.x); a0.y = fmaf(c0, v[j].y, a0.y);
                a0.z = fmaf(c0, v[j].z, a0.z); a0.w = fmaf(c0, v[j].w, a0.w);
                a1.x = fmaf(c1, v[j].x, a1.x); a1.y = fmaf(c1, v[j].y, a1.y);
                a1.z = fmaf(c1, v[j].z, a1.z); a1.w = fmaf(c1, v[j].w, a1.w);
                a2.x = fmaf(c2, v[j].x, a2.x); a2.y = fmaf(c2, v[j].y, a2.y);
                a2.z = fmaf(c2, v[j].z, a2.z); a2.w = fmaf(c2, v[j].w, a2.w);
            }
        }
    }
    sred[y][0][d4] = a0;
    sred[y][1][d4] = a1;
    sred[y][2][d4] = a2;
    __syncthreads();

    if (tid < 240) {
        const int kk = tid / 80;
        const int dd = tid % 80;
        if (dd < ND4) {
            float4 s = sred[0][kk][dd];
            #pragma unroll
            for (int w = 1; w < WAYS; w++) {
                const float4 v = sred[w][kk][dd];
                s.x += v.x; s.y += v.y; s.z += v.z; s.w += v.w;
            }
            g_part4[((b * CH + chunk) * 3 + kk) * ND4 + dd] = s;
        }
    }
}

// ---------------------------------------------------------------------------
// Kernel 2 (fused epilogue): one block per batch, 512 threads, quarter-split.
// Dyn smem (f4): W[12416] + sg[225] + qpart[384] + hbuf[96] = 13121 f4.
// Bounded unrolls keep regs low (no spills).
// ---------------------------------------------------------------------------
#define SG_OFF   12416
#define QP_OFF   12641          // quarter partials: 4*384 floats = 384 f4
#define HB_OFF   13025          // h buffer: 384 floats = 96 f4
#define EPI_SMEM (13121 * 16)   // 209936 B

__global__ __launch_bounds__(512, 1) void epilogue_kernel(
    const float* __restrict__ conv_w,
    const float* __restrict__ conv_b,
    const float* __restrict__ fc3_w,
    const float* __restrict__ fc3_b,
    const float* __restrict__ fc4_w,
    const float* __restrict__ fc4_b,
    const float* __restrict__ fc5_w,
    const float* __restrict__ fc5_b,
    const float* __restrict__ fc_w,
    const float* __restrict__ fc_b,
    float* __restrict__ out)
{
    extern __shared__ float4 dyn[];
    float4* W   = dyn;                       // conv_w [128][75] / fc_w [128][97]
    float4* sg  = dyn + SG_OFF;              // g[3*75]
    float*  qp  = (float*)(dyn + QP_OFF);    // [4][384] quarter partials
    float*  hb  = (float*)(dyn + HB_OFF);    // [384] h
    __shared__ float sSk[3];

    const int tid  = threadIdx.x;
    const int warp = tid >> 5;
    const int lane = tid & 31;
    const int b    = blockIdx.x;

    // S_k (warps 0-2)
    if (warp < 3) {
        const float* wks[3] = {fc3_w, fc4_w, fc5_w};
        const float* w = wks[warp];
        const int n = NL - (warp + 3);
        float s = 0.f;
        for (int l = lane; l < n; l += 32) s += w[l];
        #pragma unroll
        for (int off = 16; off > 0; off >>= 1)
            s += __shfl_xor_sync(0xFFFFFFFFu, s, off);
        if (lane == 0) sSk[warp] = s;
    }

    // Phase A: stage conv_w (9600 f4; bounded unroll) + reduce g_part chunks
    {
        const float4* cwg = (const float4*)conv_w;
        #pragma unroll 4
        for (int j = tid; j < NC * ND4; j += 512)
            W[j] = __ldg(&cwg[j]);
    }
    if (tid < 225) {
        const float4* p = &g_part4[b * (CH * 225) + tid];
        float4 s = p[0];
        #pragma unroll
        for (int ch = 1; ch < CH; ch++) {
            const float4 v = p[ch * 225];
            s.x += v.x; s.y += v.y; s.z += v.z; s.w += v.w;
        }
        sg[tid] = s;
    }
    __syncthreads();

    // Phase B: conv dots. thread -> (c = tid&127, q = tid>>7); q covers 19|19|19|18 f4
    const int c = tid & 127;
    const int q = tid >> 7;
    {
        const int i0 = q * 19;
        const int i1 = (q == 3) ? ND4 : (i0 + 19);
        float s0 = 0.f, s1 = 0.f, s2 = 0.f;
        #pragma unroll 4
        for (int i = i0; i < i1; i++) {
            const float4 w  = W[c * ND4 + i];   // conflict-free (12c mod 32 per phase)
            const float4 g0 = sg[i];            // broadcast
            const float4 g1 = sg[75 + i];
            const float4 g2 = sg[150 + i];
            s0 = fmaf(w.x, g0.x, s0); s0 = fmaf(w.y, g0.y, s0);
            s0 = fmaf(w.z, g0.z, s0); s0 = fmaf(w.w, g0.w, s0);
            s1 = fmaf(w.x, g1.x, s1); s1 = fmaf(w.y, g1.y, s1);
            s1 = fmaf(w.z, g1.z, s1); s1 = fmaf(w.w, g1.w, s1);
            s2 = fmaf(w.x, g2.x, s2); s2 = fmaf(w.y, g2.y, s2);
            s2 = fmaf(w.z, g2.z, s2); s2 = fmaf(w.w, g2.w, s2);
        }
        qp[q * 384 + 0 * NC + c] = s0;
        qp[q * 384 + 1 * NC + c] = s1;
        qp[q * 384 + 2 * NC + c] = s2;
    }
    __syncthreads();

    // Phase C: combine quarters -> h; restage fc_w (12288 f4) padded stride 97
    if (tid < NC) {
        const float cb = conv_b[tid];
        const float bks[3] = {fc3_b[0], fc4_b[0], fc5_b[0]};
        #pragma unroll
        for (int kk = 0; kk < 3; kk++) {
            float h = qp[0 * 384 + kk * NC + tid] + qp[1 * 384 + kk * NC + tid]
                    + qp[2 * 384 + kk * NC + tid] + qp[3 * 384 + kk * NC + tid];
            hb[kk * NC + tid] = h + cb * sSk[kk] + bks[kk];
        }
    }
    __syncthreads();   // qp consumed; fc_w staging may overwrite W freely
    {
        const float4* fwg = (const float4*)fc_w;
        #pragma unroll 4
        for (int j = tid; j < NC * 96; j += 512) {
            const int r = j / 96, i = j % 96;
            W[r * 97 + i] = __ldg(&fwg[j]);
        }
    }
    __syncthreads();

    // Phase D: fc dots. thread -> (c, q); 24 f4 each
    {
        const float4* h4 = (const float4*)hb;
        float o = 0.f;
        #pragma unroll 4
        for (int i = q * 24; i < q * 24 + 24; i++) {
            const float4 w = W[c * 97 + i];   // conflict-free (4c mod 32 per phase)
            const float4 h = h4[i];           // broadcast
            o = fmaf(w.x, h.x, o); o = fmaf(w.y, h.y, o);
            o = fmaf(w.z, h.z, o); o = fmaf(w.w, h.w, o);
        }
        qp[q * NC + c] = o;
    }
    __syncthreads();

    if (tid < NC)
        out[b * NC + tid] = qp[tid] + qp[NC + tid] + qp[2 * NC + tid]
                          + qp[3 * NC + tid] + fc_b[tid];
}

// ---------------------------------------------------------------------------
extern "C" void kernel_launch(void* const* d_in, const int* in_sizes, int n_in,
                              void* d_out, int out_size) {
    const int*   x       = (const int*)  d_in[0];
    const float* embed_w = (const float*)d_in[1];
    const float* conv_w  = (const float*)d_in[2];
    const float* conv_b  = (const float*)d_in[3];
    const float* fc3_w   = (const float*)d_in[4];
    const float* fc3_b   = (const float*)d_in[5];
    const float* fc4_w   = (const float*)d_in[6];
    const float* fc4_b   = (const float*)d_in[7];
    const float* fc5_w   = (const float*)d_in[8];
    const float* fc5_b   = (const float*)d_in[9];
    const float* fc_w    = (const float*)d_in[10];
    const float* fc_b    = (const float*)d_in[11];
    float* out = (float*)d_out;

    static int smem_set = 0;
    if (!smem_set) {
        cudaFuncSetAttribute(epilogue_kernel,
                             cudaFuncAttributeMaxDynamicSharedMemorySize, EPI_SMEM);
        smem_set = 1;
    }

    gather_kernel<<<NB * CH, 320>>>(x, embed_w, fc3_w, fc4_w, fc5_w);
    epilogue_kernel<<<NB, 512, EPI_SMEM>>>(conv_w, conv_b, fc3_w, fc3_b,
                                           fc4_w, fc4_b, fc5_w, fc5_b,
                                           fc_w, fc_b, out);
}

// round 10
// speedup vs baseline: 1.0317x; 1.0317x over previous
#include <cuda_runtime.h>
#include <cuda_bf16.h>

#define NB 64      // batch
#define NL 512     // sequence length
#define ND 300     // embed dim
#define ND4 75     // float4 lanes per row
#define NC 128     // channels
#define CH 8       // token chunks per batch
#define TPC 64     // tokens per gather block
#define WAYS 4
#define JPER 16    // tokens per way

// Scratch (__device__ globals per allocation rules)
__device__ float4 g_part4[NB * CH * 3 * ND4];  // partial g sums
__device__ float  g_h[NB * 384];               // h[b][384]

// ---------------------------------------------------------------------------
// Kernel 1: embedding gather + weighted partial reduction. (unchanged)
// ---------------------------------------------------------------------------
__global__ __launch_bounds__(320, 3) void gather_kernel(
    const int*   __restrict__ x,
    const float* __restrict__ embed_w,
    const float* __restrict__ fc3_w,
    const float* __restrict__ fc4_w,
    const float* __restrict__ fc5_w)
{
    const int b     = blockIdx.x >> 3;
    const int chunk = blockIdx.x & 7;

    __shared__ int    sidx[TPC];
    __shared__ float  sc[3][TPC];
    __shared__ float4 sred[WAYS][3][80];

    const int tid = threadIdx.x;
    const int d4  = tid % 80;
    const int y   = tid / 80;

    if (tid < 192) {
        const int kk = tid >> 6;
        const int tt = tid & 63;
        const int t  = chunk * TPC + tt;
        const float* wk = (kk == 0) ? fc3_w : (kk == 1) ? fc4_w : fc5_w;
        const int k = kk + 3;
        int lo = t - k + 1; if (lo < 0) lo = 0;
        int hi = t; const int lim = NL - k - 1; if (hi > lim) hi = lim;
        float s = 0.f;
        #pragma unroll 5
        for (int l = lo; l <= hi; l++) s += __ldg(&wk[l]);
        sc[kk][tt] = s;
    } else if (tid < 256) {
        const int tt = tid - 192;
        sidx[tt] = __ldg(&x[b * NL + chunk * TPC + tt]);
    }
    __syncthreads();

    float4 a0 = make_float4(0.f, 0.f, 0.f, 0.f);
    float4 a1 = a0, a2 = a0;

    if (d4 < ND4) {
        const float4* emb4 = (const float4*)embed_w;
        #pragma unroll
        for (int bb = 0; bb < 2; bb++) {
            int    rix[8];
            float4 v[8];
            #pragma unroll
            for (int j = 0; j < 8; j++) rix[j] = sidx[y * JPER + bb * 8 + j];
            #pragma unroll
            for (int j = 0; j < 8; j++) v[j] = __ldg(&emb4[rix[j] * ND4 + d4]);
            #pragma unroll
            for (int j = 0; j < 8; j++) {
                const int jj = y * JPER + bb * 8 + j;
                const float c0 = sc[0][jj], c1 = sc[1][jj], c2 = sc[2][jj];
                a0.x = fmaf(c0, v[j].x, a0.x); a0.y = fmaf(c0, v[j].y, a0.y);
                a0.z = fmaf(c0, v[j].z, a0.z); a0.w = fmaf(c0, v[j].w, a0.w);
                a1.x = fmaf(c1, v[j].x, a1.x); a1.y = fmaf(c1, v[j].y, a1.y);
                a1.z = fmaf(c1, v[j].z, a1.z); a1.w = fmaf(c1, v[j].w, a1.w);
                a2.x = fmaf(c2, v[j].x, a2.x); a2.y = fmaf(c2, v[j].y, a2.y);
                a2.z = fmaf(c2, v[j].z, a2.z); a2.w = fmaf(c2, v[j].w, a2.w);
            }
        }
    }
    sred[y][0][d4] = a0;
    sred[y][1][d4] = a1;
    sred[y][2][d4] = a2;
    __syncthreads();

    if (tid < 240) {
        const int kk = tid / 80;
        const int dd = tid % 80;
        if (dd < ND4) {
            float4 s = sred[0][kk][dd];
            #pragma unroll
            for (int w = 1; w < WAYS; w++) {
                const float4 v = sred[w][kk][dd];
                s.x += v.x; s.y += v.y; s.z += v.z; s.w += v.w;
            }
            g_part4[((b * CH + chunk) * 3 + kk) * ND4 + dd] = s;
        }
    }
}

// ---------------------------------------------------------------------------
// Kernel 2: sim. grid (4 ctiles, 64 batches) = 256 blocks, 128 threads.
// Thread = (c in 0..31, q in 0..3); per-thread private partial dots, smem combine.
// smem: cw[2400 f4] + sg[225 f4] + qp[384 f] = 43 584 B -> good residency.
// ---------------------------------------------------------------------------
__global__ __launch_bounds__(128) void sim_kernel(
    const float* __restrict__ conv_w,
    const float* __restrict__ conv_b,
    const float* __restrict__ fc3_w,
    const float* __restrict__ fc3_b,
    const float* __restrict__ fc4_w,
    const float* __restrict__ fc4_b,
    const float* __restrict__ fc5_w,
    const float* __restrict__ fc5_b)
{
    __shared__ float4 cw_s[32 * ND4];   // [32][75]
    __shared__ float4 sg[3 * ND4];      // g[3*75]
    __shared__ float  qp[4 * 384];      // quarter partials [q][kk*32+ ... ] -> [q][3][32]
    __shared__ float  sSk[3];

    const int tid  = threadIdx.x;
    const int warp = tid >> 5;
    const int lane = tid & 31;
    const int ct   = blockIdx.x;        // 0..3
    const int b    = blockIdx.y;        // 0..63
    const int c0   = ct * 32;

    // S_k (warps 0-2)
    if (warp < 3) {
        const float* wks[3] = {fc3_w, fc4_w, fc5_w};
        const float* w = wks[warp];
        const int n = NL - (warp + 3);
        float s = 0.f;
        for (int l = lane; l < n; l += 32) s += w[l];
        #pragma unroll
        for (int off = 16; off > 0; off >>= 1)
            s += __shfl_xor_sync(0xFFFFFFFFu, s, off);
        if (lane == 0) sSk[warp] = s;
    }

    // Stage conv_w tile (2400 f4, coalesced; bounded unroll)
    {
        const float4* cwg = (const float4*)conv_w;
        #pragma unroll 4
        for (int j = tid; j < 32 * ND4; j += 128)
            cw_s[j] = __ldg(&cwg[c0 * ND4 + j]);
    }
    // Reduce 8 chunk partials -> sg (225 positions, 2 per thread)
    #pragma unroll
    for (int i = tid; i < 225; i += 128) {
        const float4* p = &g_part4[b * (CH * 225) + i];
        float4 s = p[0];
        #pragma unroll
        for (int ch = 1; ch < CH; ch++) {
            const float4 v = p[ch * 225];
            s.x += v.x; s.y += v.y; s.z += v.z; s.w += v.w;
        }
        sg[i] = s;
    }
    __syncthreads();

    // Dots: thread (c = lane, q = warp); q covers 19|19|19|18 f4
    const int c = lane;
    const int q = warp;
    {
        const int i0 = q * 19;
        const int i1 = (q == 3) ? ND4 : (i0 + 19);
        float s0 = 0.f, s1 = 0.f, s2 = 0.f;
        #pragma unroll 4
        for (int i = i0; i < i1; i++) {
            const float4 w  = cw_s[c * ND4 + i];  // conflict-free (12c mod 32)
            const float4 g0 = sg[i];              // broadcast
            const float4 g1 = sg[75 + i];
            const float4 g2 = sg[150 + i];
            s0 = fmaf(w.x, g0.x, s0); s0 = fmaf(w.y, g0.y, s0);
            s0 = fmaf(w.z, g0.z, s0); s0 = fmaf(w.w, g0.w, s0);
            s1 = fmaf(w.x, g1.x, s1); s1 = fmaf(w.y, g1.y, s1);
            s1 = fmaf(w.z, g1.z, s1); s1 = fmaf(w.w, g1.w, s1);
            s2 = fmaf(w.x, g2.x, s2); s2 = fmaf(w.y, g2.y, s2);
            s2 = fmaf(w.z, g2.z, s2); s2 = fmaf(w.w, g2.w, s2);
        }
        qp[q * 96 + 0 * 32 + c] = s0;
        qp[q * 96 + 1 * 32 + c] = s1;
        qp[q * 96 + 2 * 32 + c] = s2;
    }
    __syncthreads();

    // Combine quarters -> h, write global. 96 threads: (kk, c)
    if (tid < 96) {
        const int kk = tid / 32;
        const int cc = tid % 32;
        float h = qp[0 * 96 + kk * 32 + cc] + qp[1 * 96 + kk * 32 + cc]
                + qp[2 * 96 + kk * 32 + cc] + qp[3 * 96 + kk * 32 + cc];
        const float bk = (kk == 0) ? fc3_b[0] : (kk == 1) ? fc4_b[0] : fc5_b[0];
        h += conv_b[c0 + cc] * sSk[kk] + bk;
        g_h[b * 384 + kk * NC + c0 + cc] = h;
    }
}

// ---------------------------------------------------------------------------
// Kernel 3: fc. grid (4 cotiles, 64 batches) = 256 blocks, 128 threads.
// smem: fw[32*97 f4 padded] + sh[96 f4] + qp[128 f] = 51 712 B.
// ---------------------------------------------------------------------------
__global__ __launch_bounds__(128) void fc_kernel(
    const float* __restrict__ fc_w,
    const float* __restrict__ fc_b,
    float* __restrict__ out)
{
    __shared__ float4 fw_s[32 * 97];    // padded stride 97
    __shared__ float4 sh[96];           // h[b]
    __shared__ float  qp[128];

    const int tid = threadIdx.x;
    const int ct  = blockIdx.x;
    const int b   = blockIdx.y;
    const int c0  = ct * 32;

    {
        const float4* fwg = (const float4*)fc_w;
        #pragma unroll 4
        for (int j = tid; j < 32 * 96; j += 128) {
            const int r = j / 96, i = j % 96;
            fw_s[r * 97 + i] = __ldg(&fwg[c0 * 96 + j]);
        }
        if (tid < 96) sh[tid] = ((const float4*)g_h)[b * 96 + tid];
    }
    __syncthreads();

    const int co = tid & 31;
    const int q  = tid >> 5;
    {
        float o = 0.f;
        #pragma unroll 4
        for (int i = q * 24; i < q * 24 + 24; i++) {
            const float4 w = fw_s[co * 97 + i];  // conflict-free (4co mod 32)
            const float4 h = sh[i];              // broadcast
            o = fmaf(w.x, h.x, o); o = fmaf(w.y, h.y, o);
            o = fmaf(w.z, h.z, o); o = fmaf(w.w, h.w, o);
        }
        qp[q * 32 + co] = o;
    }
    __syncthreads();

    if (tid < 32)
        out[b * NC + c0 + tid] = qp[tid] + qp[32 + tid] + qp[64 + tid]
                               + qp[96 + tid] + fc_b[c0 + tid];
}

// ---------------------------------------------------------------------------
extern "C" void kernel_launch(void* const* d_in, const int* in_sizes, int n_in,
                              void* d_out, int out_size) {
    const int*   x       = (const int*)  d_in[0];
    const float* embed_w = (const float*)d_in[1];
    const float* conv_w  = (const float*)d_in[2];
    const float* conv_b  = (const float*)d_in[3];
    const float* fc3_w   = (const float*)d_in[4];
    const float* fc3_b   = (const float*)d_in[5];
    const float* fc4_w   = (const float*)d_in[6];
    const float* fc4_b   = (const float*)d_in[7];
    const float* fc5_w   = (const float*)d_in[8];
    const float* fc5_b   = (const float*)d_in[9];
    const float* fc_w    = (const float*)d_in[10];
    const float* fc_b    = (const float*)d_in[11];
    float* out = (float*)d_out;

    gather_kernel<<<NB * CH, 320>>>(x, embed_w, fc3_w, fc4_w, fc5_w);
    sim_kernel<<<dim3(4, NB), 128>>>(conv_w, conv_b, fc3_w, fc3_b,
                                     fc4_w, fc4_b, fc5_w, fc5_b);
    fc_kernel<<<dim3(4, NB), 128>>>(fc_w, fc_b, out);
}